// round 2
// baseline (speedup 1.0000x reference)
#include <cuda_runtime.h>
#include <math.h>

#define N_NODES 50000
#define N_EDGES 800000
#define DIN 512
#define DH 128
#define DOUTC 7
#define BN_EPS 1e-5f

// ---------------- scratch (no cudaMalloc allowed) ----------------
__device__ float g_deg[N_NODES];
__device__ float g_dinv[N_NODES];
__device__ float g_h1[N_NODES * DH];   // raw GEMM output (scatter source)
__device__ float g_h2[N_NODES * DH];   // layer-1 aggregation accumulator
__device__ float g_h3[N_NODES * DH];   // layer-2 aggregation accumulator
__device__ float g_alpha1[DH];
__device__ float g_beta1[DH];
__device__ float g_alpha2[DH];
__device__ float g_beta2[DH];

// ---------------- degree / dinv ----------------
__global__ void k_deg_init() {
    int i = blockIdx.x * blockDim.x + threadIdx.x;
    if (i < N_NODES) g_deg[i] = 1.0f;  // self-loop
}

__global__ void k_deg_count(const int* __restrict__ ei) {
    int e = blockIdx.x * blockDim.x + threadIdx.x;
    if (e < N_EDGES) {
        int d = ei[N_EDGES + e];
        atomicAdd(&g_deg[d], 1.0f);
    }
}

__global__ void k_dinv() {
    int i = blockIdx.x * blockDim.x + threadIdx.x;
    if (i < N_NODES) g_dinv[i] = rsqrtf(fmaxf(g_deg[i], 1.0f));
}

// ---------------- fold bias + BN(eval) into per-channel affine ----------------
__global__ void k_bnparam(const float* __restrict__ b, const float* __restrict__ g,
                          const float* __restrict__ be, const float* __restrict__ rm,
                          const float* __restrict__ rv,
                          float* __restrict__ alpha, float* __restrict__ beta) {
    int c = threadIdx.x;
    if (c < DH) {
        float a = g[c] * rsqrtf(rv[c] + BN_EPS);
        alpha[c] = a;
        beta[c]  = (b[c] - rm[c]) * a + be[c];
    }
}

// ---------------- SGEMM: C[M,128] = act(A)[M,K] * B[K,128] ----------------
// BM=128, BN=128, BK=16, 256 threads, 8x8 micro-tile.
// AFFINE: apply relu(alpha1*a + beta1) to A elements (channel = k index).
// Epilogue writes Craw = acc and Cself = acc * dinv[row]^2.
template<bool AFFINE>
__global__ __launch_bounds__(256) void sgemm128(
    const float* __restrict__ A, const float* __restrict__ B,
    float* __restrict__ Craw, float* __restrict__ Cself, int M, int K)
{
    __shared__ float As[16][128];   // transposed: As[k][m]
    __shared__ float Bs[16][128];

    int tid = threadIdx.x;
    int tx = tid & 15;
    int ty = tid >> 4;
    int m0 = blockIdx.x * 128;

    float acc[8][8];
#pragma unroll
    for (int i = 0; i < 8; i++)
#pragma unroll
        for (int j = 0; j < 8; j++) acc[i][j] = 0.0f;

    for (int k0 = 0; k0 < K; k0 += 16) {
#pragma unroll
        for (int it = 0; it < 2; it++) {
            int v = tid + it * 256;        // 0..511 float4 slots
            int r = v >> 2;                // row within tile 0..127
            int c = (v & 3) * 4;           // k offset 0,4,8,12
            int row = m0 + r;
            float4 a = make_float4(0.f, 0.f, 0.f, 0.f);
            if (row < M) a = *(const float4*)(A + (size_t)row * K + k0 + c);
            if (AFFINE) {
                int ch = k0 + c;
                a.x = fmaxf(fmaf(a.x, g_alpha1[ch + 0], g_beta1[ch + 0]), 0.f);
                a.y = fmaxf(fmaf(a.y, g_alpha1[ch + 1], g_beta1[ch + 1]), 0.f);
                a.z = fmaxf(fmaf(a.z, g_alpha1[ch + 2], g_beta1[ch + 2]), 0.f);
                a.w = fmaxf(fmaf(a.w, g_alpha1[ch + 3], g_beta1[ch + 3]), 0.f);
            }
            As[c + 0][r] = a.x; As[c + 1][r] = a.y;
            As[c + 2][r] = a.z; As[c + 3][r] = a.w;
        }
#pragma unroll
        for (int it = 0; it < 2; it++) {
            int v = tid + it * 256;
            int r = v >> 5;
            int c = (v & 31) * 4;
            *(float4*)(&Bs[r][c]) = *(const float4*)(B + (size_t)(k0 + r) * 128 + c);
        }
        __syncthreads();

#pragma unroll
        for (int k = 0; k < 16; k++) {
            float ra[8], rb[8];
            *(float4*)(ra)     = *(const float4*)(&As[k][ty * 8]);
            *(float4*)(ra + 4) = *(const float4*)(&As[k][ty * 8 + 4]);
            *(float4*)(rb)     = *(const float4*)(&Bs[k][tx * 8]);
            *(float4*)(rb + 4) = *(const float4*)(&Bs[k][tx * 8 + 4]);
#pragma unroll
            for (int i = 0; i < 8; i++)
#pragma unroll
                for (int j = 0; j < 8; j++)
                    acc[i][j] = fmaf(ra[i], rb[j], acc[i][j]);
        }
        __syncthreads();
    }

#pragma unroll
    for (int i = 0; i < 8; i++) {
        int row = m0 + ty * 8 + i;
        if (row < M) {
            float dv = g_dinv[row];
            float nn = dv * dv;
            size_t base = (size_t)row * 128 + tx * 8;
            float4 lo = make_float4(acc[i][0], acc[i][1], acc[i][2], acc[i][3]);
            float4 hi = make_float4(acc[i][4], acc[i][5], acc[i][6], acc[i][7]);
            *(float4*)(Craw + base)     = lo;
            *(float4*)(Craw + base + 4) = hi;
            float4 slo = make_float4(lo.x * nn, lo.y * nn, lo.z * nn, lo.w * nn);
            float4 shi = make_float4(hi.x * nn, hi.y * nn, hi.z * nn, hi.w * nn);
            *(float4*)(Cself + base)     = slo;
            *(float4*)(Cself + base + 4) = shi;
        }
    }
}

// ---------------- edge scatter: warp per edge, vectorized atomic add ----------------
__global__ __launch_bounds__(256) void k_scatter(
    const float* __restrict__ h, float* __restrict__ out,
    const int* __restrict__ ei)
{
    int w = (blockIdx.x * blockDim.x + threadIdx.x) >> 5;
    int lane = threadIdx.x & 31;
    if (w >= N_EDGES) return;
    int s = ei[w];
    int d = ei[N_EDGES + w];
    float norm = g_dinv[s] * g_dinv[d];
    float4 v = ((const float4*)(h + (size_t)s * DH))[lane];
    v.x *= norm; v.y *= norm; v.z *= norm; v.w *= norm;
    float* addr = out + (size_t)d * DH + lane * 4;
    asm volatile("red.global.add.v4.f32 [%0], {%1,%2,%3,%4};"
                 :: "l"(addr), "f"(v.x), "f"(v.y), "f"(v.z), "f"(v.w)
                 : "memory");
}

// ---------------- final: relu(affine2(h)) @ Wfc + bfc, then log_softmax ----------------
__global__ __launch_bounds__(256) void k_fc_lsm(
    const float* __restrict__ h, const float* __restrict__ Wfc,
    const float* __restrict__ bfc, float* __restrict__ out)
{
    __shared__ float Ws[DH * DOUTC];
    __shared__ float bs[DOUTC];
    for (int i = threadIdx.x; i < DH * DOUTC; i += blockDim.x) Ws[i] = Wfc[i];
    if (threadIdx.x < DOUTC) bs[threadIdx.x] = bfc[threadIdx.x];
    __syncthreads();

    int row  = (blockIdx.x * blockDim.x + threadIdx.x) >> 5;
    int lane = threadIdx.x & 31;
    if (row >= N_NODES) return;

    const float* hr = h + (size_t)row * DH;
    float acc[DOUTC];
#pragma unroll
    for (int j = 0; j < DOUTC; j++) acc[j] = 0.0f;

#pragma unroll
    for (int i = 0; i < 4; i++) {
        int k = lane + i * 32;
        float hv = fmaxf(fmaf(hr[k], g_alpha2[k], g_beta2[k]), 0.f);
#pragma unroll
        for (int j = 0; j < DOUTC; j++)
            acc[j] = fmaf(hv, Ws[k * DOUTC + j], acc[j]);
    }
#pragma unroll
    for (int off = 16; off; off >>= 1)
#pragma unroll
        for (int j = 0; j < DOUTC; j++)
            acc[j] += __shfl_down_sync(0xffffffff, acc[j], off);

    if (lane == 0) {
        float m = -INFINITY;
#pragma unroll
        for (int j = 0; j < DOUTC; j++) { acc[j] += bs[j]; m = fmaxf(m, acc[j]); }
        float s = 0.0f;
#pragma unroll
        for (int j = 0; j < DOUTC; j++) s += expf(acc[j] - m);
        float lse = m + logf(s);
#pragma unroll
        for (int j = 0; j < DOUTC; j++)
            out[(size_t)row * DOUTC + j] = acc[j] - lse;
    }
}

// ---------------- launch ----------------
extern "C" void kernel_launch(void* const* d_in, const int* in_sizes, int n_in,
                              void* d_out, int out_size) {
    const float* x   = (const float*)d_in[0];
    const int*   ei  = (const int*)d_in[1];      // int32 on the wire (JAX x64 disabled)
    const float* W1  = (const float*)d_in[2];
    const float* b1  = (const float*)d_in[3];
    const float* g1  = (const float*)d_in[4];
    const float* be1 = (const float*)d_in[5];
    const float* rm1 = (const float*)d_in[6];
    const float* rv1 = (const float*)d_in[7];
    const float* W2  = (const float*)d_in[8];
    const float* b2  = (const float*)d_in[9];
    const float* g2  = (const float*)d_in[10];
    const float* be2 = (const float*)d_in[11];
    const float* rm2 = (const float*)d_in[12];
    const float* rv2 = (const float*)d_in[13];
    const float* Wfc = (const float*)d_in[14];
    const float* bfc = (const float*)d_in[15];
    float* out = (float*)d_out;

    float *p_h1, *p_h2, *p_h3, *p_a1, *p_b1s, *p_a2, *p_b2s;
    cudaGetSymbolAddress((void**)&p_h1, g_h1);
    cudaGetSymbolAddress((void**)&p_h2, g_h2);
    cudaGetSymbolAddress((void**)&p_h3, g_h3);
    cudaGetSymbolAddress((void**)&p_a1, g_alpha1);
    cudaGetSymbolAddress((void**)&p_b1s, g_beta1);
    cudaGetSymbolAddress((void**)&p_a2, g_alpha2);
    cudaGetSymbolAddress((void**)&p_b2s, g_beta2);

    const int GEMM_BLOCKS = (N_NODES + 127) / 128;

    // degrees (shared by both convs) + BN affine params
    k_deg_init<<<(N_NODES + 255) / 256, 256>>>();
    k_deg_count<<<(N_EDGES + 255) / 256, 256>>>(ei);
    k_dinv<<<(N_NODES + 255) / 256, 256>>>();
    k_bnparam<<<1, 128>>>(b1, g1, be1, rm1, rv1, p_a1, p_b1s);
    k_bnparam<<<1, 128>>>(b2, g2, be2, rm2, rv2, p_a2, p_b2s);

    // ---- layer 1: h2 = dinv^2*h1 (epilogue) + scatter(h1) ----
    sgemm128<false><<<GEMM_BLOCKS, 256>>>(x, W1, p_h1, p_h2, N_NODES, DIN);
    k_scatter<<<N_EDGES / 8, 256>>>(p_h1, p_h2, ei);

    // ---- layer 2: A = relu(affine1(h2)) applied in-tile ----
    sgemm128<true><<<GEMM_BLOCKS, 256>>>(p_h2, W2, p_h1, p_h3, N_NODES, DH);
    k_scatter<<<N_EDGES / 8, 256>>>(p_h1, p_h3, ei);

    // ---- FC + log_softmax (affine2+relu inline) ----
    k_fc_lsm<<<(N_NODES + 7) / 8, 256>>>(p_h3, Wfc, bfc, out);
}

// round 3
// speedup vs baseline: 1.1514x; 1.1514x over previous
#include <cuda_runtime.h>
#include <math.h>

#define N_NODES 50000
#define N_EDGES 800000
#define DIN 512
#define DH 128
#define DOUTC 7
#define BN_EPS 1e-5f

// ---------------- scratch (no cudaMalloc allowed) ----------------
__device__ float g_deg[N_NODES];
__device__ float g_dinv[N_NODES];
__device__ float g_h1[N_NODES * DH];   // raw GEMM output (scatter source)
__device__ float g_h2[N_NODES * DH];   // layer-1 aggregation accumulator
__device__ float g_h3[N_NODES * DH];   // layer-2 aggregation accumulator
__device__ float g_alpha1[DH];
__device__ float g_beta1[DH];
__device__ float g_alpha2[DH];
__device__ float g_beta2[DH];

// ---------------- degree / dinv ----------------
__global__ void k_deg_init() {
    int i = blockIdx.x * blockDim.x + threadIdx.x;
    if (i < N_NODES) g_deg[i] = 1.0f;  // self-loop
}

__global__ void k_deg_count(const int* __restrict__ ei) {
    int e = blockIdx.x * blockDim.x + threadIdx.x;
    if (e < N_EDGES) atomicAdd(&g_deg[ei[N_EDGES + e]], 1.0f);
}

__global__ void k_dinv() {
    int i = blockIdx.x * blockDim.x + threadIdx.x;
    if (i < N_NODES) g_dinv[i] = rsqrtf(fmaxf(g_deg[i], 1.0f));
}

// ---------------- both BN affines in one launch ----------------
__global__ void k_bnparam2(const float* __restrict__ b1, const float* __restrict__ g1,
                           const float* __restrict__ be1, const float* __restrict__ rm1,
                           const float* __restrict__ rv1,
                           const float* __restrict__ b2, const float* __restrict__ g2,
                           const float* __restrict__ be2, const float* __restrict__ rm2,
                           const float* __restrict__ rv2) {
    int c = threadIdx.x;
    if (c < DH) {
        float a = g1[c] * rsqrtf(rv1[c] + BN_EPS);
        g_alpha1[c] = a;
        g_beta1[c]  = (b1[c] - rm1[c]) * a + be1[c];
    } else {
        int d = c - DH;
        float a = g2[d] * rsqrtf(rv2[d] + BN_EPS);
        g_alpha2[d] = a;
        g_beta2[d]  = (b2[d] - rm2[d]) * a + be2[d];
    }
}

// ---------------- tf32 helpers ----------------
__device__ __forceinline__ unsigned tf32_cvt(float f) {
    unsigned u;
    asm("cvt.rna.tf32.f32 %0, %1;" : "=r"(u) : "f"(f));
    return u;
}

__device__ __forceinline__ void mma_tf32(float* d, const unsigned* a, unsigned b0, unsigned b1) {
    asm volatile(
        "mma.sync.aligned.m16n8k8.row.col.f32.tf32.tf32.f32 "
        "{%0,%1,%2,%3}, {%4,%5,%6,%7}, {%8,%9}, {%0,%1,%2,%3};"
        : "+f"(d[0]), "+f"(d[1]), "+f"(d[2]), "+f"(d[3])
        : "r"(a[0]), "r"(a[1]), "r"(a[2]), "r"(a[3]), "r"(b0), "r"(b1));
}

// ---------------- tensor-core GEMM: C[M,128] = act(A)[M,K] * B[K,128] ----------------
// tf32x3 split precision: D = AhBh + AhBl + AlBh (fp32-class accuracy).
// 256 threads = 8 warps in 4(M)x2(N); warp tile 32x64 of m16n8k8 atoms. BK=16.
// Epilogue writes Craw = acc, Cself = acc * dinv[row]^2.
#define A_STR 20
#define B_STR 136
template<bool AFFINE>
__global__ __launch_bounds__(256, 2) void gemm_tc(
    const float* __restrict__ A, const float* __restrict__ B,
    float* __restrict__ Craw, float* __restrict__ Cself, int M, int K)
{
    __shared__ float As[128 * A_STR];     // fp32 A tile (affine pre-applied)
    __shared__ float BsH[16 * B_STR];     // tf32 hi of B tile
    __shared__ float BsL[16 * B_STR];     // tf32 lo of B tile

    int tid = threadIdx.x, wid = tid >> 5, lane = tid & 31;
    int wm = wid >> 1, wn = wid & 1;
    int g = lane >> 2, t4 = lane & 3;
    int m0 = blockIdx.x * 128;

    float acc[2][8][4];
#pragma unroll
    for (int mt = 0; mt < 2; mt++)
#pragma unroll
        for (int nt = 0; nt < 8; nt++)
#pragma unroll
            for (int j = 0; j < 4; j++) acc[mt][nt][j] = 0.0f;

    for (int k0 = 0; k0 < K; k0 += 16) {
        // A tile: 128 x 16 fp32
#pragma unroll
        for (int i = 0; i < 2; i++) {
            int slot = tid + i * 256;
            int r = slot >> 2, c = (slot & 3) * 4;
            int row = m0 + r;
            float4 a = make_float4(0.f, 0.f, 0.f, 0.f);
            if (row < M) a = *(const float4*)(A + (size_t)row * K + k0 + c);
            if (AFFINE) {
                int ch = k0 + c;
                float4 al = *(const float4*)(g_alpha1 + ch);
                float4 bt = *(const float4*)(g_beta1 + ch);
                a.x = fmaxf(fmaf(a.x, al.x, bt.x), 0.f);
                a.y = fmaxf(fmaf(a.y, al.y, bt.y), 0.f);
                a.z = fmaxf(fmaf(a.z, al.z, bt.z), 0.f);
                a.w = fmaxf(fmaf(a.w, al.w, bt.w), 0.f);
            }
            *(float4*)(&As[r * A_STR + c]) = a;
        }
        // B tile: 16 x 128, split into tf32 hi/lo
#pragma unroll
        for (int i = 0; i < 2; i++) {
            int slot = tid + i * 256;
            int r = slot >> 5, c = (slot & 31) * 4;
            float4 b = *(const float4*)(B + (size_t)(k0 + r) * 128 + c);
            float4 bh, bl;
            unsigned u;
            u = tf32_cvt(b.x); bh.x = __uint_as_float(u); bl.x = __uint_as_float(tf32_cvt(b.x - __uint_as_float(u)));
            u = tf32_cvt(b.y); bh.y = __uint_as_float(u); bl.y = __uint_as_float(tf32_cvt(b.y - __uint_as_float(u)));
            u = tf32_cvt(b.z); bh.z = __uint_as_float(u); bl.z = __uint_as_float(tf32_cvt(b.z - __uint_as_float(u)));
            u = tf32_cvt(b.w); bh.w = __uint_as_float(u); bl.w = __uint_as_float(tf32_cvt(b.w - __uint_as_float(u)));
            *(float4*)(&BsH[r * B_STR + c]) = bh;
            *(float4*)(&BsL[r * B_STR + c]) = bl;
        }
        __syncthreads();

#pragma unroll
        for (int kk = 0; kk < 16; kk += 8) {
            unsigned ah[2][4], al[2][4];
#pragma unroll
            for (int mt = 0; mt < 2; mt++) {
                int mb = wm * 32 + mt * 16;
                float f0 = As[(mb + g)     * A_STR + kk + t4];
                float f1 = As[(mb + 8 + g) * A_STR + kk + t4];
                float f2 = As[(mb + g)     * A_STR + kk + 4 + t4];
                float f3 = As[(mb + 8 + g) * A_STR + kk + 4 + t4];
                ah[mt][0] = tf32_cvt(f0); al[mt][0] = tf32_cvt(f0 - __uint_as_float(ah[mt][0]));
                ah[mt][1] = tf32_cvt(f1); al[mt][1] = tf32_cvt(f1 - __uint_as_float(ah[mt][1]));
                ah[mt][2] = tf32_cvt(f2); al[mt][2] = tf32_cvt(f2 - __uint_as_float(ah[mt][2]));
                ah[mt][3] = tf32_cvt(f3); al[mt][3] = tf32_cvt(f3 - __uint_as_float(ah[mt][3]));
            }
#pragma unroll
            for (int nt = 0; nt < 8; nt++) {
                int n = wn * 64 + nt * 8 + g;
                unsigned b0h = __float_as_uint(BsH[(kk + t4)     * B_STR + n]);
                unsigned b1h = __float_as_uint(BsH[(kk + 4 + t4) * B_STR + n]);
                unsigned b0l = __float_as_uint(BsL[(kk + t4)     * B_STR + n]);
                unsigned b1l = __float_as_uint(BsL[(kk + 4 + t4) * B_STR + n]);
#pragma unroll
                for (int mt = 0; mt < 2; mt++) {
                    mma_tf32(acc[mt][nt], ah[mt], b0h, b1h);
                    mma_tf32(acc[mt][nt], ah[mt], b0l, b1l);
                    mma_tf32(acc[mt][nt], al[mt], b0h, b1h);
                }
            }
        }
        __syncthreads();
    }

    // epilogue
#pragma unroll
    for (int mt = 0; mt < 2; mt++) {
        int row0 = m0 + wm * 32 + mt * 16 + g;
        int row1 = row0 + 8;
        float n0 = 0.f, n1 = 0.f;
        if (row0 < M) { float dv = g_dinv[row0]; n0 = dv * dv; }
        if (row1 < M) { float dv = g_dinv[row1]; n1 = dv * dv; }
#pragma unroll
        for (int nt = 0; nt < 8; nt++) {
            int col = wn * 64 + nt * 8 + 2 * t4;
            if (row0 < M) {
                size_t o = (size_t)row0 * 128 + col;
                *(float2*)(Craw + o)  = make_float2(acc[mt][nt][0], acc[mt][nt][1]);
                *(float2*)(Cself + o) = make_float2(acc[mt][nt][0] * n0, acc[mt][nt][1] * n0);
            }
            if (row1 < M) {
                size_t o = (size_t)row1 * 128 + col;
                *(float2*)(Craw + o)  = make_float2(acc[mt][nt][2], acc[mt][nt][3]);
                *(float2*)(Cself + o) = make_float2(acc[mt][nt][2] * n1, acc[mt][nt][3] * n1);
            }
        }
    }
}

// ---------------- edge scatter: warp per edge, vectorized atomic add ----------------
__global__ __launch_bounds__(256) void k_scatter(
    const float* __restrict__ h, float* __restrict__ out,
    const int* __restrict__ ei)
{
    int w = (blockIdx.x * blockDim.x + threadIdx.x) >> 5;
    int lane = threadIdx.x & 31;
    if (w >= N_EDGES) return;
    int s = ei[w];
    int d = ei[N_EDGES + w];
    float norm = g_dinv[s] * g_dinv[d];
    float4 v = ((const float4*)(h + (size_t)s * DH))[lane];
    v.x *= norm; v.y *= norm; v.z *= norm; v.w *= norm;
    float* addr = out + (size_t)d * DH + lane * 4;
    asm volatile("red.global.add.v4.f32 [%0], {%1,%2,%3,%4};"
                 :: "l"(addr), "f"(v.x), "f"(v.y), "f"(v.z), "f"(v.w)
                 : "memory");
}

// ---------------- final: relu(affine2(h)) @ Wfc + bfc, then log_softmax ----------------
__global__ __launch_bounds__(256) void k_fc_lsm(
    const float* __restrict__ h, const float* __restrict__ Wfc,
    const float* __restrict__ bfc, float* __restrict__ out)
{
    __shared__ float Ws[DH * DOUTC];
    __shared__ float bs[DOUTC];
    for (int i = threadIdx.x; i < DH * DOUTC; i += blockDim.x) Ws[i] = Wfc[i];
    if (threadIdx.x < DOUTC) bs[threadIdx.x] = bfc[threadIdx.x];
    __syncthreads();

    int row  = (blockIdx.x * blockDim.x + threadIdx.x) >> 5;
    int lane = threadIdx.x & 31;
    if (row >= N_NODES) return;

    const float* hr = h + (size_t)row * DH;
    float acc[DOUTC];
#pragma unroll
    for (int j = 0; j < DOUTC; j++) acc[j] = 0.0f;

#pragma unroll
    for (int i = 0; i < 4; i++) {
        int k = lane + i * 32;
        float hv = fmaxf(fmaf(hr[k], g_alpha2[k], g_beta2[k]), 0.f);
#pragma unroll
        for (int j = 0; j < DOUTC; j++)
            acc[j] = fmaf(hv, Ws[k * DOUTC + j], acc[j]);
    }
#pragma unroll
    for (int off = 16; off; off >>= 1)
#pragma unroll
        for (int j = 0; j < DOUTC; j++)
            acc[j] += __shfl_down_sync(0xffffffff, acc[j], off);

    if (lane == 0) {
        float m = -INFINITY;
#pragma unroll
        for (int j = 0; j < DOUTC; j++) { acc[j] += bs[j]; m = fmaxf(m, acc[j]); }
        float s = 0.0f;
#pragma unroll
        for (int j = 0; j < DOUTC; j++) s += expf(acc[j] - m);
        float lse = m + logf(s);
#pragma unroll
        for (int j = 0; j < DOUTC; j++)
            out[(size_t)row * DOUTC + j] = acc[j] - lse;
    }
}

// ---------------- launch ----------------
extern "C" void kernel_launch(void* const* d_in, const int* in_sizes, int n_in,
                              void* d_out, int out_size) {
    const float* x   = (const float*)d_in[0];
    const int*   ei  = (const int*)d_in[1];
    const float* W1  = (const float*)d_in[2];
    const float* b1  = (const float*)d_in[3];
    const float* g1  = (const float*)d_in[4];
    const float* be1 = (const float*)d_in[5];
    const float* rm1 = (const float*)d_in[6];
    const float* rv1 = (const float*)d_in[7];
    const float* W2  = (const float*)d_in[8];
    const float* b2  = (const float*)d_in[9];
    const float* g2  = (const float*)d_in[10];
    const float* be2 = (const float*)d_in[11];
    const float* rm2 = (const float*)d_in[12];
    const float* rv2 = (const float*)d_in[13];
    const float* Wfc = (const float*)d_in[14];
    const float* bfc = (const float*)d_in[15];
    float* out = (float*)d_out;

    float *p_h1, *p_h2, *p_h3;
    cudaGetSymbolAddress((void**)&p_h1, g_h1);
    cudaGetSymbolAddress((void**)&p_h2, g_h2);
    cudaGetSymbolAddress((void**)&p_h3, g_h3);

    const int GEMM_BLOCKS = (N_NODES + 127) / 128;

    // prologue (4 launches so gemm1 sits at capture index 4/5)
    k_deg_init<<<(N_NODES + 255) / 256, 256>>>();
    k_deg_count<<<(N_EDGES + 255) / 256, 256>>>(ei);
    k_dinv<<<(N_NODES + 255) / 256, 256>>>();
    k_bnparam2<<<1, 256>>>(b1, g1, be1, rm1, rv1, b2, g2, be2, rm2, rv2);

    // ---- layer 1 ----
    gemm_tc<false><<<GEMM_BLOCKS, 256>>>(x, W1, p_h1, p_h2, N_NODES, DIN);
    k_scatter<<<N_EDGES / 8, 256>>>(p_h1, p_h2, ei);

    // ---- layer 2 (relu∘affine1 fused into A-tile load) ----
    gemm_tc<true><<<GEMM_BLOCKS, 256>>>(p_h2, W2, p_h1, p_h3, N_NODES, DH);
    k_scatter<<<N_EDGES / 8, 256>>>(p_h1, p_h3, ei);

    // ---- FC + log_softmax (affine2+relu inline) ----
    k_fc_lsm<<<(N_NODES + 7) / 8, 256>>>(p_h3, Wfc, bfc, out);
}

// round 4
// speedup vs baseline: 1.2632x; 1.0972x over previous
#include <cuda_runtime.h>
#include <math.h>

#define N_NODES 50000
#define N_EDGES 800000
#define DIN 512
#define DH 128
#define DOUTC 7
#define BN_EPS 1e-5f
#define SCAN_T 1024

// ---------------- scratch (no cudaMalloc allowed) ----------------
__device__ int   g_cnt[N_NODES];        // in-degree (excl. self-loop)
__device__ int   g_row[N_NODES];        // CSR row start
__device__ int   g_cursor[N_NODES];     // fill cursors
__device__ int   g_csr_src[N_EDGES];    // CSR: source node per slot
__device__ float g_csr_w[N_EDGES];      // CSR: edge weight dinv[s]*dinv[d]
__device__ float g_dinv[N_NODES];
__device__ float g_h1[N_NODES * DH];    // raw GEMM output (gather source)
__device__ float g_h2[N_NODES * DH];    // layer-1 aggregated
__device__ float g_h3[N_NODES * DH];    // layer-2 aggregated
__device__ float g_alpha1[DH];
__device__ float g_beta1[DH];
__device__ float g_alpha2[DH];
__device__ float g_beta2[DH];

// ---------------- CSR build ----------------
__global__ void k_zero() {
    int i = blockIdx.x * blockDim.x + threadIdx.x;
    if (i < N_NODES) g_cnt[i] = 0;
}

__global__ void k_hist(const int* __restrict__ ei) {
    int e = blockIdx.x * blockDim.x + threadIdx.x;
    if (e < N_EDGES) atomicAdd(&g_cnt[ei[N_EDGES + e]], 1);
}

__global__ void k_dinv() {
    int i = blockIdx.x * blockDim.x + threadIdx.x;
    if (i < N_NODES) g_dinv[i] = rsqrtf((float)(g_cnt[i] + 1));  // +1 self-loop
}

// single-block exclusive scan of g_cnt -> g_row, g_cursor
__global__ __launch_bounds__(SCAN_T) void k_scan() {
    __shared__ int sums[SCAN_T];
    int t = threadIdx.x;
    const int CH = (N_NODES + SCAN_T - 1) / SCAN_T;
    int start = t * CH;
    int end = start + CH; if (end > N_NODES) end = N_NODES;
    int s = 0;
    for (int i = start; i < end; i++) s += g_cnt[i];
    sums[t] = s;
    __syncthreads();
    for (int off = 1; off < SCAN_T; off <<= 1) {
        int v = (t >= off) ? sums[t - off] : 0;
        __syncthreads();
        sums[t] += v;
        __syncthreads();
    }
    int run = (t == 0) ? 0 : sums[t - 1];
    for (int i = start; i < end; i++) {
        g_row[i] = run;
        g_cursor[i] = run;
        run += g_cnt[i];
    }
}

__global__ void k_fill(const int* __restrict__ ei) {
    int e = blockIdx.x * blockDim.x + threadIdx.x;
    if (e < N_EDGES) {
        int s = ei[e];
        int d = ei[N_EDGES + e];
        int p = atomicAdd(&g_cursor[d], 1);
        g_csr_src[p] = s;
        g_csr_w[p] = g_dinv[s] * g_dinv[d];
    }
}

// ---------------- both BN affines in one launch ----------------
__global__ void k_bnparam2(const float* __restrict__ b1, const float* __restrict__ g1,
                           const float* __restrict__ be1, const float* __restrict__ rm1,
                           const float* __restrict__ rv1,
                           const float* __restrict__ b2, const float* __restrict__ g2,
                           const float* __restrict__ be2, const float* __restrict__ rm2,
                           const float* __restrict__ rv2) {
    int c = threadIdx.x;
    if (c < DH) {
        float a = g1[c] * rsqrtf(rv1[c] + BN_EPS);
        g_alpha1[c] = a;
        g_beta1[c]  = (b1[c] - rm1[c]) * a + be1[c];
    } else {
        int d = c - DH;
        float a = g2[d] * rsqrtf(rv2[d] + BN_EPS);
        g_alpha2[d] = a;
        g_beta2[d]  = (b2[d] - rm2[d]) * a + be2[d];
    }
}

// ---------------- tf32 helpers ----------------
__device__ __forceinline__ unsigned tf32_cvt(float f) {
    unsigned u;
    asm("cvt.rna.tf32.f32 %0, %1;" : "=r"(u) : "f"(f));
    return u;
}

__device__ __forceinline__ void mma_tf32(float* d, const unsigned* a, unsigned b0, unsigned b1) {
    asm volatile(
        "mma.sync.aligned.m16n8k8.row.col.f32.tf32.tf32.f32 "
        "{%0,%1,%2,%3}, {%4,%5,%6,%7}, {%8,%9}, {%0,%1,%2,%3};"
        : "+f"(d[0]), "+f"(d[1]), "+f"(d[2]), "+f"(d[3])
        : "r"(a[0]), "r"(a[1]), "r"(a[2]), "r"(a[3]), "r"(b0), "r"(b1));
}

// ---------------- tensor-core GEMM: C[M,128] = act(A)[M,K] * B[K,128] ----------------
// tf32x3 split precision. 256 threads = 8 warps (4M x 2N); warp tile 32x64. BK=16.
#define A_STR 20
#define B_STR 136
template<bool AFFINE>
__global__ __launch_bounds__(256, 2) void gemm_tc(
    const float* __restrict__ A, const float* __restrict__ B,
    float* __restrict__ C, int M, int K)
{
    __shared__ float As[128 * A_STR];
    __shared__ float BsH[16 * B_STR];
    __shared__ float BsL[16 * B_STR];

    int tid = threadIdx.x, wid = tid >> 5, lane = tid & 31;
    int wm = wid >> 1, wn = wid & 1;
    int g = lane >> 2, t4 = lane & 3;
    int m0 = blockIdx.x * 128;

    float acc[2][8][4];
#pragma unroll
    for (int mt = 0; mt < 2; mt++)
#pragma unroll
        for (int nt = 0; nt < 8; nt++)
#pragma unroll
            for (int j = 0; j < 4; j++) acc[mt][nt][j] = 0.0f;

    for (int k0 = 0; k0 < K; k0 += 16) {
#pragma unroll
        for (int i = 0; i < 2; i++) {
            int slot = tid + i * 256;
            int r = slot >> 2, c = (slot & 3) * 4;
            int row = m0 + r;
            float4 a = make_float4(0.f, 0.f, 0.f, 0.f);
            if (row < M) a = *(const float4*)(A + (size_t)row * K + k0 + c);
            if (AFFINE) {
                int ch = k0 + c;
                float4 al = *(const float4*)(g_alpha1 + ch);
                float4 bt = *(const float4*)(g_beta1 + ch);
                a.x = fmaxf(fmaf(a.x, al.x, bt.x), 0.f);
                a.y = fmaxf(fmaf(a.y, al.y, bt.y), 0.f);
                a.z = fmaxf(fmaf(a.z, al.z, bt.z), 0.f);
                a.w = fmaxf(fmaf(a.w, al.w, bt.w), 0.f);
            }
            *(float4*)(&As[r * A_STR + c]) = a;
        }
#pragma unroll
        for (int i = 0; i < 2; i++) {
            int slot = tid + i * 256;
            int r = slot >> 5, c = (slot & 31) * 4;
            float4 b = *(const float4*)(B + (size_t)(k0 + r) * 128 + c);
            float4 bh, bl;
            unsigned u;
            u = tf32_cvt(b.x); bh.x = __uint_as_float(u); bl.x = __uint_as_float(tf32_cvt(b.x - __uint_as_float(u)));
            u = tf32_cvt(b.y); bh.y = __uint_as_float(u); bl.y = __uint_as_float(tf32_cvt(b.y - __uint_as_float(u)));
            u = tf32_cvt(b.z); bh.z = __uint_as_float(u); bl.z = __uint_as_float(tf32_cvt(b.z - __uint_as_float(u)));
            u = tf32_cvt(b.w); bh.w = __uint_as_float(u); bl.w = __uint_as_float(tf32_cvt(b.w - __uint_as_float(u)));
            *(float4*)(&BsH[r * B_STR + c]) = bh;
            *(float4*)(&BsL[r * B_STR + c]) = bl;
        }
        __syncthreads();

#pragma unroll
        for (int kk = 0; kk < 16; kk += 8) {
            unsigned ah[2][4], al[2][4];
#pragma unroll
            for (int mt = 0; mt < 2; mt++) {
                int mb = wm * 32 + mt * 16;
                float f0 = As[(mb + g)     * A_STR + kk + t4];
                float f1 = As[(mb + 8 + g) * A_STR + kk + t4];
                float f2 = As[(mb + g)     * A_STR + kk + 4 + t4];
                float f3 = As[(mb + 8 + g) * A_STR + kk + 4 + t4];
                ah[mt][0] = tf32_cvt(f0); al[mt][0] = tf32_cvt(f0 - __uint_as_float(ah[mt][0]));
                ah[mt][1] = tf32_cvt(f1); al[mt][1] = tf32_cvt(f1 - __uint_as_float(ah[mt][1]));
                ah[mt][2] = tf32_cvt(f2); al[mt][2] = tf32_cvt(f2 - __uint_as_float(ah[mt][2]));
                ah[mt][3] = tf32_cvt(f3); al[mt][3] = tf32_cvt(f3 - __uint_as_float(ah[mt][3]));
            }
#pragma unroll
            for (int nt = 0; nt < 8; nt++) {
                int n = wn * 64 + nt * 8 + g;
                unsigned b0h = __float_as_uint(BsH[(kk + t4)     * B_STR + n]);
                unsigned b1h = __float_as_uint(BsH[(kk + 4 + t4) * B_STR + n]);
                unsigned b0l = __float_as_uint(BsL[(kk + t4)     * B_STR + n]);
                unsigned b1l = __float_as_uint(BsL[(kk + 4 + t4) * B_STR + n]);
#pragma unroll
                for (int mt = 0; mt < 2; mt++) {
                    mma_tf32(acc[mt][nt], ah[mt], b0h, b1h);
                    mma_tf32(acc[mt][nt], ah[mt], b0l, b1l);
                    mma_tf32(acc[mt][nt], al[mt], b0h, b1h);
                }
            }
        }
        __syncthreads();
    }

#pragma unroll
    for (int mt = 0; mt < 2; mt++) {
        int row0 = m0 + wm * 32 + mt * 16 + g;
        int row1 = row0 + 8;
#pragma unroll
        for (int nt = 0; nt < 8; nt++) {
            int col = wn * 64 + nt * 8 + 2 * t4;
            if (row0 < M)
                *(float2*)(C + (size_t)row0 * 128 + col) = make_float2(acc[mt][nt][0], acc[mt][nt][1]);
            if (row1 < M)
                *(float2*)(C + (size_t)row1 * 128 + col) = make_float2(acc[mt][nt][2], acc[mt][nt][3]);
        }
    }
}

// ---------------- CSR aggregation: warp per node, self-loop included ----------------
__global__ __launch_bounds__(256) void k_agg(
    const float* __restrict__ h, float* __restrict__ out)
{
    int n = (blockIdx.x * blockDim.x + threadIdx.x) >> 5;
    int lane = threadIdx.x & 31;
    if (n >= N_NODES) return;

    float dv = g_dinv[n];
    float sl = dv * dv;
    float4 acc = ((const float4*)(h + (size_t)n * DH))[lane];
    acc.x *= sl; acc.y *= sl; acc.z *= sl; acc.w *= sl;

    int beg = g_row[n];
    int cnt = g_cnt[n];
    int e = beg;
    // unroll 2 for MLP
    for (; e + 1 < beg + cnt; e += 2) {
        int s0 = g_csr_src[e];
        int s1 = g_csr_src[e + 1];
        float w0 = g_csr_w[e];
        float w1 = g_csr_w[e + 1];
        float4 v0 = ((const float4*)(h + (size_t)s0 * DH))[lane];
        float4 v1 = ((const float4*)(h + (size_t)s1 * DH))[lane];
        acc.x = fmaf(w0, v0.x, acc.x); acc.y = fmaf(w0, v0.y, acc.y);
        acc.z = fmaf(w0, v0.z, acc.z); acc.w = fmaf(w0, v0.w, acc.w);
        acc.x = fmaf(w1, v1.x, acc.x); acc.y = fmaf(w1, v1.y, acc.y);
        acc.z = fmaf(w1, v1.z, acc.z); acc.w = fmaf(w1, v1.w, acc.w);
    }
    if (e < beg + cnt) {
        int s0 = g_csr_src[e];
        float w0 = g_csr_w[e];
        float4 v0 = ((const float4*)(h + (size_t)s0 * DH))[lane];
        acc.x = fmaf(w0, v0.x, acc.x); acc.y = fmaf(w0, v0.y, acc.y);
        acc.z = fmaf(w0, v0.z, acc.z); acc.w = fmaf(w0, v0.w, acc.w);
    }
    ((float4*)(out + (size_t)n * DH))[lane] = acc;
}

// ---------------- final: relu(affine2(h)) @ Wfc + bfc, then log_softmax ----------------
__global__ __launch_bounds__(256) void k_fc_lsm(
    const float* __restrict__ h, const float* __restrict__ Wfc,
    const float* __restrict__ bfc, float* __restrict__ out)
{
    __shared__ float Ws[DH * DOUTC];
    __shared__ float bs[DOUTC];
    for (int i = threadIdx.x; i < DH * DOUTC; i += blockDim.x) Ws[i] = Wfc[i];
    if (threadIdx.x < DOUTC) bs[threadIdx.x] = bfc[threadIdx.x];
    __syncthreads();

    int row  = (blockIdx.x * blockDim.x + threadIdx.x) >> 5;
    int lane = threadIdx.x & 31;
    if (row >= N_NODES) return;

    const float* hr = h + (size_t)row * DH;
    float acc[DOUTC];
#pragma unroll
    for (int j = 0; j < DOUTC; j++) acc[j] = 0.0f;

#pragma unroll
    for (int i = 0; i < 4; i++) {
        int k = lane + i * 32;
        float hv = fmaxf(fmaf(hr[k], g_alpha2[k], g_beta2[k]), 0.f);
#pragma unroll
        for (int j = 0; j < DOUTC; j++)
            acc[j] = fmaf(hv, Ws[k * DOUTC + j], acc[j]);
    }
#pragma unroll
    for (int off = 16; off; off >>= 1)
#pragma unroll
        for (int j = 0; j < DOUTC; j++)
            acc[j] += __shfl_down_sync(0xffffffff, acc[j], off);

    if (lane == 0) {
        float m = -INFINITY;
#pragma unroll
        for (int j = 0; j < DOUTC; j++) { acc[j] += bs[j]; m = fmaxf(m, acc[j]); }
        float s = 0.0f;
#pragma unroll
        for (int j = 0; j < DOUTC; j++) s += expf(acc[j] - m);
        float lse = m + logf(s);
#pragma unroll
        for (int j = 0; j < DOUTC; j++)
            out[(size_t)row * DOUTC + j] = acc[j] - lse;
    }
}

// ---------------- launch ----------------
extern "C" void kernel_launch(void* const* d_in, const int* in_sizes, int n_in,
                              void* d_out, int out_size) {
    const float* x   = (const float*)d_in[0];
    const int*   ei  = (const int*)d_in[1];
    const float* W1  = (const float*)d_in[2];
    const float* b1  = (const float*)d_in[3];
    const float* g1  = (const float*)d_in[4];
    const float* be1 = (const float*)d_in[5];
    const float* rm1 = (const float*)d_in[6];
    const float* rv1 = (const float*)d_in[7];
    const float* W2  = (const float*)d_in[8];
    const float* b2  = (const float*)d_in[9];
    const float* g2  = (const float*)d_in[10];
    const float* be2 = (const float*)d_in[11];
    const float* rm2 = (const float*)d_in[12];
    const float* rv2 = (const float*)d_in[13];
    const float* Wfc = (const float*)d_in[14];
    const float* bfc = (const float*)d_in[15];
    float* out = (float*)d_out;

    float *p_h1, *p_h2, *p_h3;
    cudaGetSymbolAddress((void**)&p_h1, g_h1);
    cudaGetSymbolAddress((void**)&p_h2, g_h2);
    cudaGetSymbolAddress((void**)&p_h3, g_h3);

    const int GEMM_BLOCKS = (N_NODES + 127) / 128;
    const int NODE_BLOCKS = (N_NODES + 255) / 256;
    const int EDGE_BLOCKS = (N_EDGES + 255) / 256;
    const int WARP_NODE_BLOCKS = (N_NODES + 7) / 8;

    // 0..2: histogram + dinv
    k_zero<<<NODE_BLOCKS, 256>>>();
    k_hist<<<EDGE_BLOCKS, 256>>>(ei);
    k_dinv<<<NODE_BLOCKS, 256>>>();

    // 3: GEMM1 (capture index 3 for ncu)
    gemm_tc<false><<<GEMM_BLOCKS, 256>>>(x, W1, p_h1, N_NODES, DIN);

    // 4..6: CSR build + BN params (independent of GEMM1 output)
    k_scan<<<1, SCAN_T>>>();
    k_fill<<<EDGE_BLOCKS, 256>>>(ei);
    k_bnparam2<<<1, 256>>>(b1, g1, be1, rm1, rv1, b2, g2, be2, rm2, rv2);

    // 7: aggregate layer 1 (self-loop fused)
    k_agg<<<WARP_NODE_BLOCKS, 256>>>(p_h1, p_h2);

    // 8: GEMM2 (relu∘affine1 fused into A-tile load)
    gemm_tc<true><<<GEMM_BLOCKS, 256>>>(p_h2, W2, p_h1, N_NODES, DH);

    // 9: aggregate layer 2
    k_agg<<<WARP_NODE_BLOCKS, 256>>>(p_h1, p_h3);

    // 10: FC + log_softmax (affine2+relu inline)
    k_fc_lsm<<<(N_NODES + 7) / 8, 256>>>(p_h3, Wfc, bfc, out);
}